// round 1
// baseline (speedup 1.0000x reference)
#include <cuda_runtime.h>
#include <math.h>

#define W_ 192
#define H_ 192
#define D_ 160
#define CHUNK 80
#define NPLANES (CHUNK + 4)

// Global accumulator for the lncc sum (scratch: __device__ global, no allocs).
__device__ double g_acc;

__global__ void init_acc_k() { g_acc = 0.0; }

__global__ void __launch_bounds__(512, 1)
lncc_main_k(const float* __restrict__ src, const float* __restrict__ tgt)
{
    // tile[0] = source plane (36 x 36 halo tile, rows padded to 40 for 16B align)
    // tile[1] = target plane
    __shared__ float tile[2][36][40];
    // rs[ch][haloRow][x] : x-direction 5-tap sums per channel
    __shared__ float rs[5][36][32];
    __shared__ float wsum[16];

    const int tx  = threadIdx.x;
    const int ty  = threadIdx.y;
    const int tid = ty * 32 + tx;
    const int x0  = blockIdx.x * 32;
    const int y0  = blockIdx.y * 32;
    const int b   = blockIdx.z >> 1;
    const int z0  = (blockIdx.z & 1) * CHUNK;

    const float* baseS = src + (size_t)b * (D_ * H_ * W_);
    const float* baseT = tgt + (size_t)b * (D_ * H_ * W_);

    // ---- precompute per-thread load slots (2 * 36 * 36 = 2592 elements) ----
    int goff[6];
    int soff[6];
    unsigned flags = 0; // bit k: slot used; bit k+8: gmem in-range; bit k+16: is source
    #pragma unroll
    for (int k = 0; k < 6; k++) {
        goff[k] = 0; soff[k] = 0;
        int i = tid + k * 512;
        if (i < 2592) {
            flags |= 1u << k;
            int isS = (i < 1296) ? 1 : 0;
            int j   = isS ? i : (i - 1296);
            int row = j / 36;
            int col = j - row * 36;
            int gy  = y0 + row - 2;
            int gx  = x0 + col - 2;
            soff[k] = (isS ? 0 : 1440) + row * 40 + col;
            if ((unsigned)gy < (unsigned)H_ && (unsigned)gx < (unsigned)W_) {
                flags |= 1u << (k + 8);
                goff[k] = gy * W_ + gx;
            }
            if (isS) flags |= 1u << (k + 16);
        }
    }

    float pf[6];
    auto issue_loads = [&](int zp) {
        const bool zin  = (zp >= 0) && (zp < D_);
        const int pbase = zp * (H_ * W_);
        #pragma unroll
        for (int k = 0; k < 6; k++) {
            float v = 0.f;
            if (zin && (flags & (1u << (k + 8)))) {
                const float* p = (flags & (1u << (k + 16))) ? baseS : baseT;
                v = __ldg(p + pbase + goff[k]);
            }
            pf[k] = v;
        }
    };
    auto store_tiles = [&]() {
        float* ts = &tile[0][0][0];
        #pragma unroll
        for (int k = 0; k < 6; k++)
            if (flags & (1u << k)) ts[soff[k]] = pf[k];
    };

    // ---- register ring buffer for z-direction 5-tap sum ----
    float ring[5][2][5];
    float run[2][5];
    #pragma unroll
    for (int s = 0; s < 5; s++)
        #pragma unroll
        for (int p = 0; p < 2; p++)
            #pragma unroll
            for (int c = 0; c < 5; c++) ring[s][p][c] = 0.f;
    #pragma unroll
    for (int p = 0; p < 2; p++)
        #pragma unroll
        for (int c = 0; c < 5; c++) run[p][c] = 0.f;

    float acc = 0.f;
    const int zstart = z0 - 2;
    const int yb = 2 * ty;

    issue_loads(zstart);

    for (int basep = 0; basep < NPLANES; basep += 5) {
        #pragma unroll
        for (int s = 0; s < 5; s++) {           // s is compile-time after unroll
            const int ip = basep + s;
            if (ip >= NPLANES) break;
            const int zp = zstart + ip;

            __syncthreads();                    // everyone done reading rs/tile
            store_tiles();
            issue_loads(zp + 1);                // prefetch next plane (hidden)
            __syncthreads();                    // tile ready

            // ---- step 2: x-direction sliding 5-tap sums, 4 windows/group ----
            if (tid < 288) {
                const int r  = tid >> 3;
                const int x4 = (tid & 7) << 2;
                const float* rowS = &tile[0][r][x4];
                const float* rowT = &tile[1][r][x4];
                float4 a0 = *(const float4*)(rowS);
                float4 a1 = *(const float4*)(rowS + 4);
                float4 b0 = *(const float4*)(rowT);
                float4 b1 = *(const float4*)(rowT + 4);
                float sc[8] = {a0.x,a0.y,a0.z,a0.w,a1.x,a1.y,a1.z,a1.w};
                float tc[8] = {b0.x,b0.y,b0.z,b0.w,b1.x,b1.y,b1.z,b1.w};

                float S[4], T[4], SS[4], TT[4], ST[4];
                float s0=0.f,t0=0.f,ss0=0.f,tt0=0.f,st0=0.f;
                #pragma unroll
                for (int j = 0; j < 5; j++) {
                    s0 += sc[j]; t0 += tc[j];
                    ss0 = fmaf(sc[j], sc[j], ss0);
                    tt0 = fmaf(tc[j], tc[j], tt0);
                    st0 = fmaf(sc[j], tc[j], st0);
                }
                S[0]=s0; T[0]=t0; SS[0]=ss0; TT[0]=tt0; ST[0]=st0;
                #pragma unroll
                for (int w = 1; w < 4; w++) {
                    S[w]  = S[w-1]  - sc[w-1] + sc[w+4];
                    T[w]  = T[w-1]  - tc[w-1] + tc[w+4];
                    SS[w] = SS[w-1] - sc[w-1]*sc[w-1] + sc[w+4]*sc[w+4];
                    TT[w] = TT[w-1] - tc[w-1]*tc[w-1] + tc[w+4]*tc[w+4];
                    ST[w] = ST[w-1] - sc[w-1]*tc[w-1] + sc[w+4]*tc[w+4];
                }
                *(float4*)&rs[0][r][x4] = make_float4(S[0],S[1],S[2],S[3]);
                *(float4*)&rs[1][r][x4] = make_float4(T[0],T[1],T[2],T[3]);
                *(float4*)&rs[2][r][x4] = make_float4(SS[0],SS[1],SS[2],SS[3]);
                *(float4*)&rs[3][r][x4] = make_float4(TT[0],TT[1],TT[2],TT[3]);
                *(float4*)&rs[4][r][x4] = make_float4(ST[0],ST[1],ST[2],ST[3]);
            }
            __syncthreads();                    // rs ready

            // ---- step 3: y-direction sums, 2 stacked pixels per thread ----
            float n0[5], n1[5];
            #pragma unroll
            for (int c = 0; c < 5; c++) {
                float v0 = rs[c][yb+0][tx];
                float v1 = rs[c][yb+1][tx];
                float v2 = rs[c][yb+2][tx];
                float v3 = rs[c][yb+3][tx];
                float v4 = rs[c][yb+4][tx];
                float v5 = rs[c][yb+5][tx];
                float sm = ((v0+v1)+(v2+v3))+v4;
                n0[c] = sm;
                n1[c] = sm - v0 + v5;
            }

            // ---- z-direction: incremental ring update (slot s compile-time) --
            #pragma unroll
            for (int c = 0; c < 5; c++) {
                run[0][c]    += n0[c] - ring[s][0][c];
                ring[s][0][c] = n0[c];
                run[1][c]    += n1[c] - ring[s][1][c];
                ring[s][1][c] = n1[c];
            }

            const int zo = zp - 2;
            if (zo >= z0 && zo < z0 + CHUNK) {
                const float inv = 1.f / 125.f;
                #pragma unroll
                for (int p = 0; p < 2; p++) {
                    float sm = run[p][0] * inv;
                    float tm = run[p][1] * inv;
                    float sv = fmaf(-sm, sm, run[p][2] * inv);
                    float tv = fmaf(-tm, tm, run[p][3] * inv);
                    float cr = fmaf(-sm, tm, run[p][4] * inv);
                    float den = fmaf(sv, tv, 1e-5f);
                    acc += __fdividef(cr * cr, den);
                }
            }
        }
    }

    // ---- block reduction -> global double accumulator ----
    #pragma unroll
    for (int o = 16; o > 0; o >>= 1)
        acc += __shfl_xor_sync(0xffffffffu, acc, o);
    if ((tid & 31) == 0) wsum[tid >> 5] = acc;
    __syncthreads();
    if (tid == 0) {
        float bsum = 0.f;
        #pragma unroll
        for (int i = 0; i < 16; i++) bsum += wsum[i];
        atomicAdd(&g_acc, (double)bsum);
    }
}

__global__ void finalize_k(float* out)
{
    const double n = 2.0 * 160.0 * 192.0 * 192.0;  // 11796480
    double mean = g_acc / n;
    float loss = (float)(1.0 - mean);
    if (isnan(loss) || isinf(loss)) loss = 1.0f;
    out[0] = loss;
}

extern "C" void kernel_launch(void* const* d_in, const int* in_sizes, int n_in,
                              void* d_out, int out_size)
{
    (void)in_sizes; (void)n_in; (void)out_size;
    const float* src = (const float*)d_in[0];
    const float* tgt = (const float*)d_in[1];

    init_acc_k<<<1, 1>>>();
    lncc_main_k<<<dim3(W_ / 32, H_ / 32, 2 * (D_ / CHUNK)), dim3(32, 16)>>>(src, tgt);
    finalize_k<<<1, 1>>>((float*)d_out);
}